// round 4
// baseline (speedup 1.0000x reference)
#include <cuda_runtime.h>

#define NN 8192
#define D 64
#define DO 128
#define K 16
#define SEG 8
#define JSEG (NN/SEG)       // 1024 j per block column
#define TI 128
#define TJ 128
#define NTILES (JSEG/TJ)    // 8
#define PA 68               // float2 pitch for a/b tiles (conflict-free frags)
#define PD 132              // float pitch for dist tile (conflict-free epilogue)

// Scratch (no allocs allowed)
__device__ float g_sq[NN];
__device__ float g_p[NN * DO];
__device__ float g_q[NN * DO];
__device__ float2 g_xhl[NN * D];          // {tf32_hi, tf32_lo} per element
__device__ unsigned long long g_ck[NN * SEG * K];

__device__ __forceinline__ unsigned tf32_cvt(float v) {
    unsigned u;
    asm("cvt.rna.tf32.f32 %0, %1;" : "=r"(u) : "f"(v));
    return u;
}

__device__ __forceinline__ void mma_tf32(float* c, const unsigned* a, const unsigned* b) {
    asm volatile(
        "mma.sync.aligned.m16n8k8.row.col.f32.tf32.tf32.f32 "
        "{%0,%1,%2,%3}, {%4,%5,%6,%7}, {%8,%9}, {%0,%1,%2,%3};"
        : "+f"(c[0]), "+f"(c[1]), "+f"(c[2]), "+f"(c[3])
        : "r"(a[0]), "r"(a[1]), "r"(a[2]), "r"(a[3]), "r"(b[0]), "r"(b[1]));
}

// ---------------------------------------------------------------------------
// Kernel 1: sq norms, p = x@(W1a-W1b)+b1, q = x@W1b, and tf32 hi/lo split.
// ---------------------------------------------------------------------------
__global__ __launch_bounds__(256) void pq_kernel(const float* __restrict__ x,
                                                 const float* __restrict__ W1,
                                                 const float* __restrict__ b1) {
    __shared__ float sx[8 * D];
    const int i0 = blockIdx.x * 8;
    const int t = threadIdx.x;

    for (int u = t; u < 8 * D; u += 256) sx[u] = x[i0 * D + u];
    __syncthreads();

    // tf32 split writeout
    #pragma unroll
    for (int u = t; u < 8 * D; u += 256) {
        float v = sx[u];
        unsigned h = tf32_cvt(v);
        float hf = __uint_as_float(h);
        unsigned l = tf32_cvt(v - hf);
        g_xhl[(size_t)i0 * D + u] = make_float2(hf, __uint_as_float(l));
    }

    if (t < 8) {
        float s = 0.f;
        #pragma unroll
        for (int d = 0; d < D; d++) { float v = sx[t * D + d]; s = fmaf(v, v, s); }
        g_sq[i0 + t] = s;
    }

    float acc[8];
    #pragma unroll
    for (int m = 0; m < 8; m++) acc[m] = 0.f;

    if (t < DO) {
        const int c = t;
        for (int d = 0; d < D; d++) {
            float w = W1[d * DO + c] - W1[(D + d) * DO + c];
            #pragma unroll
            for (int m = 0; m < 8; m++) acc[m] = fmaf(sx[m * D + d], w, acc[m]);
        }
        float bb = b1[c];
        #pragma unroll
        for (int m = 0; m < 8; m++) g_p[(size_t)(i0 + m) * DO + c] = acc[m] + bb;
    } else {
        const int c = t - DO;
        for (int d = 0; d < D; d++) {
            float w = W1[(D + d) * DO + c];
            #pragma unroll
            for (int m = 0; m < 8; m++) acc[m] = fmaf(sx[m * D + d], w, acc[m]);
        }
        #pragma unroll
        for (int m = 0; m < 8; m++) g_q[(size_t)(i0 + m) * DO + c] = acc[m];
    }
}

// ---------------------------------------------------------------------------
// Kernel 2: kNN via 3xTF32 tensor-core distance GEMM + fused top-k scan.
// grid = (NN/TI, SEG), block = 256 (8 warps). Warp w: rows (w&3)*32 (2 m-tiles
// of m16), cols (w>>2)*64 (8 n-tiles of n8). Dist tile j-major in smem;
// threads 0..127 scan their row keeping a sorted register top-16.
// ---------------------------------------------------------------------------
struct KnnSmem {
    float2 a[TI][PA];       // [i][k] {hi,lo}
    float2 b[TJ][PA];       // [j][k] {hi,lo}
    float dist[TJ][PD];     // [j][i]
    float sqi[TI];
    float sqj[TJ];
};
#define KNN_SMEM_BYTES sizeof(KnnSmem)

__global__ __launch_bounds__(256, 1) void knn_kernel() {
    extern __shared__ char smraw[];
    KnnSmem& sm = *reinterpret_cast<KnnSmem*>(smraw);
    const int t = threadIdx.x;
    const int lane = t & 31;
    const int w = t >> 5;
    const int gid = lane >> 2;
    const int ctid = lane & 3;
    const int m0 = (w & 3) * 32;
    const int n0 = (w >> 2) * 64;
    const int ib = blockIdx.x * TI;
    const int s = blockIdx.y;

    const float4* xg = reinterpret_cast<const float4*>(g_xhl);

    // Stage A tile once (rows ib..ib+127, 32 float4 per row).
    for (int u = t; u < TI * 32; u += 256) {
        int i = u >> 5, q = u & 31;
        float4 v = xg[(size_t)(ib + i) * 32 + q];
        *reinterpret_cast<float4*>(&sm.a[i][q * 2]) = v;
    }
    if (t < TI) sm.sqi[t] = g_sq[ib + t];

    float kd[K];
    int   kj[K];
    #pragma unroll
    for (int n = 0; n < K; n++) { kd[n] = 3.4e38f; kj[n] = 0; }

    #pragma unroll 1
    for (int tile = 0; tile < NTILES; tile++) {
        const int jb = s * JSEG + tile * TJ;

        for (int u = t; u < TJ * 32; u += 256) {
            int j = u >> 5, q = u & 31;
            float4 v = xg[(size_t)(jb + j) * 32 + q];
            *reinterpret_cast<float4*>(&sm.b[j][q * 2]) = v;
        }
        if (t < TJ) sm.sqj[t] = g_sq[jb + t];
        __syncthreads();   // B/dist ready to use; prior scans complete

        float acc[2][8][4];
        #pragma unroll
        for (int mt = 0; mt < 2; mt++)
            #pragma unroll
            for (int nt = 0; nt < 8; nt++)
                #pragma unroll
                for (int e = 0; e < 4; e++) acc[mt][nt][e] = 0.f;

        #pragma unroll
        for (int ks = 0; ks < 8; ks++) {
            const int k0 = ks * 8;
            unsigned ah[2][4], al[2][4], bh[8][2], bl[8][2];
            #pragma unroll
            for (int mt = 0; mt < 2; mt++) {
                int r = m0 + mt * 16 + gid;
                float2 v0 = sm.a[r][k0 + ctid];
                float2 v1 = sm.a[r + 8][k0 + ctid];
                float2 v2 = sm.a[r][k0 + ctid + 4];
                float2 v3 = sm.a[r + 8][k0 + ctid + 4];
                ah[mt][0] = __float_as_uint(v0.x); al[mt][0] = __float_as_uint(v0.y);
                ah[mt][1] = __float_as_uint(v1.x); al[mt][1] = __float_as_uint(v1.y);
                ah[mt][2] = __float_as_uint(v2.x); al[mt][2] = __float_as_uint(v2.y);
                ah[mt][3] = __float_as_uint(v3.x); al[mt][3] = __float_as_uint(v3.y);
            }
            #pragma unroll
            for (int nt = 0; nt < 8; nt++) {
                int n = n0 + nt * 8 + gid;
                float2 u0 = sm.b[n][k0 + ctid];
                float2 u1 = sm.b[n][k0 + ctid + 4];
                bh[nt][0] = __float_as_uint(u0.x); bl[nt][0] = __float_as_uint(u0.y);
                bh[nt][1] = __float_as_uint(u1.x); bl[nt][1] = __float_as_uint(u1.y);
            }
            #pragma unroll
            for (int mt = 0; mt < 2; mt++)
                #pragma unroll
                for (int nt = 0; nt < 8; nt++) {
                    mma_tf32(acc[mt][nt], ah[mt], bh[nt]);
                    mma_tf32(acc[mt][nt], ah[mt], bl[nt]);
                    mma_tf32(acc[mt][nt], al[mt], bh[nt]);
                }
        }

        // Epilogue: dist = sqi + sqj - 2*dot -> j-major smem tile.
        #pragma unroll
        for (int mt = 0; mt < 2; mt++) {
            #pragma unroll
            for (int nt = 0; nt < 8; nt++) {
                int r0 = m0 + mt * 16 + gid, r1 = r0 + 8;
                int c0 = n0 + nt * 8 + 2 * ctid, c1 = c0 + 1;
                float s0 = sm.sqi[r0], s1 = sm.sqi[r1];
                float t0 = sm.sqj[c0], t1 = sm.sqj[c1];
                sm.dist[c0][r0] = fmaf(-2.f, acc[mt][nt][0], s0 + t0);
                sm.dist[c1][r0] = fmaf(-2.f, acc[mt][nt][1], s0 + t1);
                sm.dist[c0][r1] = fmaf(-2.f, acc[mt][nt][2], s1 + t0);
                sm.dist[c1][r1] = fmaf(-2.f, acc[mt][nt][3], s1 + t1);
            }
        }
        __syncthreads();   // dist tile complete

        // Scan: thread t<128 owns row t.
        if (t < TI) {
            #pragma unroll 4
            for (int jj = 0; jj < TJ; jj++) {
                float dv = sm.dist[jj][t];
                if (dv < kd[K - 1]) {
                    kd[K - 1] = dv; kj[K - 1] = jb + jj;
                    #pragma unroll
                    for (int n = K - 1; n > 0; n--) {
                        if (kd[n] < kd[n - 1]) {
                            float td = kd[n]; kd[n] = kd[n - 1]; kd[n - 1] = td;
                            int   tj = kj[n]; kj[n] = kj[n - 1]; kj[n - 1] = tj;
                        }
                    }
                }
            }
        }
    }

    if (t < TI) {
        unsigned long long* dst = g_ck + ((size_t)(ib + t) * SEG + s) * K;
        #pragma unroll
        for (int n = 0; n < K; n++) {
            unsigned u = __float_as_uint(kd[n]);
            u = (u & 0x80000000u) ? ~u : (u | 0x80000000u);  // total order
            dst[n] = ((unsigned long long)u << 32) | (unsigned)kj[n];
        }
    }
}

// ---------------------------------------------------------------------------
// Kernel 3: merge SEG x 16 candidates per row, aggregate, apply W2.
// ---------------------------------------------------------------------------
__global__ __launch_bounds__(128) void agg_kernel(const float* __restrict__ W2,
                                                  const float* __restrict__ b2,
                                                  float* __restrict__ out) {
    __shared__ unsigned long long skey[SEG * K];
    __shared__ int snbr[K];
    __shared__ float sr[DO];
    const int i = blockIdx.x;
    const int t = threadIdx.x;

    skey[t] = g_ck[(size_t)i * SEG * K + t];
    __syncthreads();
    {
        unsigned long long mk = skey[t];
        int rank = 0;
        #pragma unroll 4
        for (int u = 0; u < SEG * K; u++) rank += (skey[u] < mk);
        if (rank < K) snbr[rank] = (int)(mk & 0xFFFFFFFFull);
    }
    __syncthreads();

    float p = g_p[(size_t)i * DO + t];
    float acc = 0.f;
    #pragma unroll
    for (int n = 0; n < K; n++) {
        int j = snbr[n];
        acc += fmaxf(p + g_q[(size_t)j * DO + t], 0.f);
    }
    sr[t] = acc * (1.f / K);
    __syncthreads();

    float o = b2[t];
    #pragma unroll 8
    for (int d = 0; d < DO; d++)
        o = fmaf(sr[d], W2[d * DO + t], o);
    out[(size_t)i * DO + t] = o;
}

// ---------------------------------------------------------------------------
extern "C" void kernel_launch(void* const* d_in, const int* in_sizes, int n_in,
                              void* d_out, int out_size) {
    const float* x  = (const float*)d_in[0];
    const float* W1 = (const float*)d_in[1];
    const float* b1 = (const float*)d_in[2];
    const float* W2 = (const float*)d_in[3];
    const float* b2 = (const float*)d_in[4];
    float* out = (float*)d_out;

    cudaFuncSetAttribute(knn_kernel, cudaFuncAttributeMaxDynamicSharedMemorySize,
                         (int)KNN_SMEM_BYTES);

    pq_kernel<<<NN / 8, 256>>>(x, W1, b1);
    knn_kernel<<<dim3(NN / TI, SEG), 256, KNN_SMEM_BYTES>>>();
    agg_kernel<<<NN, 128>>>(W2, b2, out);
}